// round 8
// baseline (speedup 1.0000x reference)
#include <cuda_runtime.h>
#include <cstdint>

// Problem constants
#define CCH    384
#define NPIX   1024          // 32*32
#define NIMG   16            // only first n=16 rows matter
#define KTOP   20
#define PTOT   96
#define NREM   76            // P - K
#define NUNSEL 1004          // 1024 - 20
#define CHUNKS 8             // conv blocks per image
#define CHPER  48            // channels per conv block
#define NBATCH 12            // 48 / 4 planes per batch
#define NSLICE 32            // CHUNKS * 4 groups
#define PLROW  36
#define PLSZ   (PLROW * 34)

// Scratch (device globals; all counters self-reset each launch)
__device__ float g_partial[NIMG * NSLICE * NPIX];   // [img][slice][pix]
__device__ int   g_invperm[NUNSEL];
__device__ int   g_cnt[NIMG];
__device__ int   g_permdone;
__device__ int   g_findone;

__device__ __forceinline__ uint32_t rotl32(uint32_t x, int d) {
    return (x << d) | (x >> (32 - d));
}

// Threefry-2x32, 20 rounds (matches JAX threefry2x32_p)
__device__ __forceinline__ void threefry2x32(uint32_t k0, uint32_t k1,
                                             uint32_t x0, uint32_t x1,
                                             uint32_t& o0, uint32_t& o1) {
    uint32_t k2 = k0 ^ k1 ^ 0x1BD11BDAu;
#define TF_RND(r) { x0 += x1; x1 = rotl32(x1, (r)); x1 ^= x0; }
    x0 += k0; x1 += k1;
    TF_RND(13) TF_RND(15) TF_RND(26) TF_RND(6)
    x0 += k1; x1 += k2 + 1u;
    TF_RND(17) TF_RND(29) TF_RND(16) TF_RND(24)
    x0 += k2; x1 += k0 + 2u;
    TF_RND(13) TF_RND(15) TF_RND(26) TF_RND(6)
    x0 += k0; x1 += k1 + 3u;
    TF_RND(17) TF_RND(29) TF_RND(16) TF_RND(24)
    x0 += k1; x1 += k2 + 4u;
    TF_RND(13) TF_RND(15) TF_RND(26) TF_RND(6)
    x0 += k2; x1 += k0 + 5u;
#undef TF_RND
    o0 = x0; o1 = x1;
}

union SmemU {
    struct {
        float planes[2][4][PLSZ];          // 39168 B
        float wsm[CHPER * 10];             //  1920 B
    } conv;
    struct {
        unsigned long long lists[(KTOP + 1) * 32];  // 5376 B
        int invp[NUNSEL];                           // 4016 B
        int flag[NPIX];                             // 4096 B
        int wc[32];
        int last;
    } fin;
    uint32_t bits[NUNSEL];                 // 4016 B (perm block)
};

__global__ __launch_bounds__(1024, 1)
void patch_vote_fused(const float* __restrict__ feature,
                      const float* __restrict__ dww,
                      const float* __restrict__ pww,
                      float* __restrict__ out) {
    __shared__ __align__(16) SmemU sm;
    int tid = threadIdx.x;

    // =========================== permutation block =========================
    if (blockIdx.x == 0) {
        uint32_t s0, s1;
        threefry2x32(0u, 42u, 0u, 1u, s0, s1);
        if (tid < NUNSEL) {
            uint32_t b1, b2;
            threefry2x32(s0, s1, 0u, (uint32_t)tid, b1, b2);
            sm.bits[tid] = b1 ^ b2;          // partitionable 32-bit fold
        }
        __syncthreads();
        if (tid < NUNSEL) {
            uint32_t bi = sm.bits[tid];
            const uint4* b4 = reinterpret_cast<const uint4*>(sm.bits);
            int rank = 0;
#pragma unroll 4
            for (int q4 = 0; q4 < NUNSEL / 4; q4++) {
                uint4 v = b4[q4];
                int q = q4 * 4;
                rank += (v.x < bi) || (v.x == bi && (q    ) < tid);
                rank += (v.y < bi) || (v.y == bi && (q + 1) < tid);
                rank += (v.z < bi) || (v.z == bi && (q + 2) < tid);
                rank += (v.w < bi) || (v.w == bi && (q + 3) < tid);
            }
            g_invperm[tid] = (rank < NREM) ? rank : -1;
        }
        __threadfence();
        __syncthreads();
        if (tid == 0) atomicExch(&g_permdone, 1);   // release (fence above)
        return;
    }

    // ============================= conv blocks =============================
    int id    = blockIdx.x - 1;       // 0..127
    int img   = id >> 3;
    int chunk = id & 7;
    int c0    = chunk * CHPER;
    int g     = tid >> 8;             // warp-group 0..3 -> plane index
    int s     = tid & 255;            // thread within group

    // halo ring zero (132 cells per plane, 8 planes)
    for (int i = tid; i < 8 * 132; i += 1024) {
        int pl = i / 132, r = i - pl * 132;
        int row, col;
        if (r < 34)       { row = 0;             col = r; }
        else if (r < 68)  { row = 33;            col = r - 34; }
        else if (r < 100) { row = 1 + (r - 68);  col = 0; }
        else              { row = 1 + (r - 100); col = 33; }
        (&sm.conv.planes[0][0][0])[pl * PLSZ + row * PLROW + col] = 0.f;
    }
    if (tid < CHPER * 10) {
        int ch = tid / 10, k = tid - ch * 10;
        sm.conv.wsm[tid] = (k < 9) ? __ldg(dww + (size_t)(c0 + ch) * 9 + k)
                                   : __ldg(pww + c0 + ch);
    }

    // 2x2 output tile per thread within the group's plane
    int tx = s & 15, ty = s >> 4;
    int px = tx * 2, py = ty * 2;

    // float4 load -> smem mapping
    int lp = s * 4;
    int ly = lp >> 5, lx = lp & 31;
    int dstoff = (ly + 1) * PLROW + lx + 1;

    const float4* f4 = reinterpret_cast<const float4*>(
        feature + ((size_t)img * CCH + c0) * NPIX);

    // prefetch: vB = batch b+1's channel, vA = batch b+2's channel
    float4 v0 = f4[(0 * 4 + g) * 256 + s];
    float4 vB = f4[(1 * 4 + g) * 256 + s];
    float4 vA = f4[(2 * 4 + g) * 256 + s];
    __syncthreads();                  // halo + weights done
    {
        float* d = &sm.conv.planes[0][g][dstoff];
        d[0] = v0.x; d[1] = v0.y; d[2] = v0.z; d[3] = v0.w;
    }
    __syncthreads();                  // buffer 0 ready

    float acc00 = 0.f, acc01 = 0.f, acc10 = 0.f, acc11 = 0.f;

#pragma unroll
    for (int b = 0; b < NBATCH; b++) {
        int cur = b & 1;
        if (b + 1 < NBATCH) {         // store batch b+1 into other buffer
            float* d = &sm.conv.planes[cur ^ 1][g][dstoff];
            d[0] = vB.x; d[1] = vB.y; d[2] = vB.z; d[3] = vB.w;
            vB = vA;
            if (b + 3 < NBATCH)
                vA = f4[((b + 3) * 4 + g) * 256 + s];
        }

        const float* wp = sm.conv.wsm + (b * 4 + g) * 10;
        float w0 = wp[0], w1 = wp[1], w2 = wp[2];
        float w3 = wp[3], w4 = wp[4], w5 = wp[5];
        float w6 = wp[6], w7 = wp[7], w8 = wp[8];
        float pwc = wp[9];

        const float2* p2 = reinterpret_cast<const float2*>(
            &sm.conv.planes[cur][g][py * PLROW + px]);
        float2 q00 = p2[0],  q01 = p2[1];
        float2 q10 = p2[18], q11 = p2[19];
        float2 q20 = p2[36], q21 = p2[37];
        float2 q30 = p2[54], q31 = p2[55];
        float a00=q00.x, a01=q00.y, a02=q01.x, a03=q01.y;
        float a10=q10.x, a11=q10.y, a12=q11.x, a13=q11.y;
        float a20=q20.x, a21=q20.y, a22=q21.x, a23=q21.y;
        float a30=q30.x, a31=q30.y, a32=q31.x, a33=q31.y;

        float s00 = w0*a00 + w1*a01 + w2*a02
                  + w3*a10 + w4*a11 + w5*a12
                  + w6*a20 + w7*a21 + w8*a22;
        float s01 = w0*a01 + w1*a02 + w2*a03
                  + w3*a11 + w4*a12 + w5*a13
                  + w6*a21 + w7*a22 + w8*a23;
        float s10 = w0*a10 + w1*a11 + w2*a12
                  + w3*a20 + w4*a21 + w5*a22
                  + w6*a30 + w7*a31 + w8*a32;
        float s11 = w0*a11 + w1*a12 + w2*a13
                  + w3*a21 + w4*a22 + w5*a23
                  + w6*a31 + w7*a32 + w8*a33;

        acc00 = fmaf(pwc, s00, acc00);
        acc01 = fmaf(pwc, s01, acc01);
        acc10 = fmaf(pwc, s10, acc10);
        acc11 = fmaf(pwc, s11, acc11);

        __syncthreads();              // readers of cur done; cur^1 ready
    }

    // write this group's slice (slice = chunk*4 + g)
    {
        float2* o2 = reinterpret_cast<float2*>(
            g_partial + ((size_t)img * NSLICE + chunk * 4 + g) * NPIX);
        float2 r0; r0.x = acc00; r0.y = acc01;
        float2 r1; r1.x = acc10; r1.y = acc11;
        o2[(py * 32 + px) >> 1]       = r0;
        o2[((py + 1) * 32 + px) >> 1] = r1;
    }

    // last-block election (threadFenceReduction pattern)
    __threadfence();
    __syncthreads();
    if (tid == 0) {
        int old = atomicAdd(&g_cnt[img], 1);
        sm.fin.last = (old == CHUNKS - 1) ? 1 : 0;
        if (old == CHUNKS - 1) __threadfence();     // acquire
    }
    __syncthreads();
    if (!sm.fin.last) return;

    // ============================ finalize (top-k) =========================
    int lane = tid & 31, warp = tid >> 5;
    sm.fin.flag[tid] = 0;

    // wait for permutation block (all blocks co-resident: safe spin)
    if (tid == 0) {
        while (atomicAdd(&g_permdone, 0) == 0) {}
        __threadfence();
    }
    __syncthreads();
    if (tid < NUNSEL) sm.fin.invp[tid] = g_invperm[tid];

    // deterministic slice reduction: 32 independent loads, pairwise tree
    const float* pp = g_partial + (size_t)img * NSLICE * NPIX + tid;
    float a[NSLICE];
#pragma unroll
    for (int c = 0; c < NSLICE; c++)
        a[c] = __ldg(pp + (size_t)c * NPIX);
#pragma unroll
    for (int st = 1; st < NSLICE; st <<= 1)
#pragma unroll
        for (int c = 0; c < NSLICE; c += 2 * st)
            a[c] += a[c + st];
    float val = a[0];

    // orderable key: (monotone float bits : 1023 - pix) -> max == JAX order
    uint32_t fb = __float_as_uint(val);
    fb = (fb & 0x80000000u) ? ~fb : (fb | 0x80000000u);
    unsigned long long key =
        ((unsigned long long)fb << 32) | (uint32_t)(NPIX - 1 - tid);

    // per-warp bitonic sort, DESCENDING. Keys unique.
#pragma unroll
    for (int k = 2; k <= 32; k <<= 1) {
#pragma unroll
        for (int j = k >> 1; j > 0; j >>= 1) {
            unsigned long long o = __shfl_xor_sync(0xffffffffu, key, j);
            bool dirAsc  = ((lane & k) != 0);
            bool isLower = ((lane & j) == 0);
            bool takeMin = (dirAsc == isLower);
            key = takeMin ? (key < o ? key : o) : (key > o ? key : o);
        }
    }
    if (lane <= KTOP)
        sm.fin.lists[lane * 32 + warp] = (lane < KTOP) ? key : 0ull;
    __syncthreads();

    // exact 32-way tournament merge on warp 0, REDUX-based rounds
    if (warp == 0) {
        int h = 0;
        unsigned long long head = sm.fin.lists[lane];
        for (int r = 0; r < KTOP; r++) {
            uint32_t hi = (uint32_t)(head >> 32);
            uint32_t lo = (uint32_t)head;
            uint32_t m1 = __reduce_max_sync(0xffffffffu, hi);
            uint32_t lo2 = (hi == m1) ? lo : 0u;
            uint32_t m2 = __reduce_max_sync(0xffffffffu, lo2);
            if (hi == m1 && lo == m2) {             // unique winner
                int pix = NPIX - 1 - (int)(lo & 1023u);
                int X = pix & 31, Y = pix >> 5;
                out[              img * PTOT + r] = (float)(X < 1 ? 1 : X);
                out[NIMG * PTOT + img * PTOT + r] = (float)(Y < 1 ? 1 : Y);
                sm.fin.flag[pix] = 1;
                h++;
                head = sm.fin.lists[h * 32 + lane]; // row 20 = sentinel
            }
        }
    }
    __syncthreads();

    // unselected positions via ballot + warp-0 scan of warp counts
    bool sel = (sm.fin.flag[tid] != 0);
    unsigned bal = __ballot_sync(0xffffffffu, sel);
    if (lane == 0) sm.fin.wc[warp] = __popc(bal);
    __syncthreads();
    if (warp == 0) {
        int v = sm.fin.wc[lane], sc = v;
#pragma unroll
        for (int off = 1; off < 32; off <<= 1) {
            int o = __shfl_up_sync(0xffffffffu, sc, off);
            if (lane >= off) sc += o;
        }
        sm.fin.wc[lane] = sc - v;     // exclusive prefix
    }
    __syncthreads();
    int before = sm.fin.wc[warp] + __popc(bal & ((1u << lane) - 1u));

    if (!sel) {
        int u = tid - before;         // position among unselected (0..1003)
        int j = sm.fin.invp[u];
        if (j >= 0) {
            int X = tid & 31, Y = tid >> 5;
            out[              img * PTOT + KTOP + j] = (float)(X < 1 ? 1 : X);
            out[NIMG * PTOT + img * PTOT + KTOP + j] = (float)(Y < 1 ? 1 : Y);
        }
    }

    // counter resets for graph replay (this block is the last for its image)
    __syncthreads();
    if (tid == 0) {
        atomicExch(&g_cnt[img], 0);
        int f = atomicAdd(&g_findone, 1);
        if (f == NIMG - 1) {
            atomicExch(&g_permdone, 0);
            atomicExch(&g_findone, 0);
        }
    }
}

extern "C" void kernel_launch(void* const* d_in, const int* in_sizes, int n_in,
                              void* d_out, int out_size) {
    const float* feature = (const float*)d_in[0];
    const float* dww     = (const float*)d_in[1];
    const float* pww     = (const float*)d_in[3];
    float* out = (float*)d_out;

    patch_vote_fused<<<1 + NIMG * CHUNKS, 1024>>>(feature, dww, pww, out);
}

// round 9
// speedup vs baseline: 2.3358x; 2.3358x over previous
#include <cuda_runtime.h>
#include <cstdint>

// Problem constants
#define CCH    384
#define NPIX   1024          // 32*32
#define NIMG   16            // only first n=16 rows matter
#define KTOP   20
#define PTOT   96
#define NREM   76            // P - K
#define NUNSEL 1004          // 1024 - 20
#define NCHUNK 16            // conv blocks per image
#define CHPER  24            // 384 / 16
#define NBATCH 6             // 24 channels / 4 planes per batch
#define NPERMBLK 16
#define ELEM_PER_PB 63       // 16*63 = 1008 >= 1004
#define PLROW  36
#define PLSZ   (PLROW * 34)
#define NPASS  4             // finalize: 1024 px / 256 threads

// Scratch (device globals; counters self-reset each launch)
__device__ float g_partial[NIMG * NCHUNK * NPIX];   // [img][chunk][pix]
__device__ int   g_invperm[NUNSEL];
__device__ int   g_cnt[NIMG];
__device__ int   g_permdone;
__device__ int   g_findone;

__device__ __forceinline__ uint32_t rotl32(uint32_t x, int d) {
    return (x << d) | (x >> (32 - d));
}

// Threefry-2x32, 20 rounds (matches JAX threefry2x32_p)
__device__ __forceinline__ void threefry2x32(uint32_t k0, uint32_t k1,
                                             uint32_t x0, uint32_t x1,
                                             uint32_t& o0, uint32_t& o1) {
    uint32_t k2 = k0 ^ k1 ^ 0x1BD11BDAu;
#define TF_RND(r) { x0 += x1; x1 = rotl32(x1, (r)); x1 ^= x0; }
    x0 += k0; x1 += k1;
    TF_RND(13) TF_RND(15) TF_RND(26) TF_RND(6)
    x0 += k1; x1 += k2 + 1u;
    TF_RND(17) TF_RND(29) TF_RND(16) TF_RND(24)
    x0 += k2; x1 += k0 + 2u;
    TF_RND(13) TF_RND(15) TF_RND(26) TF_RND(6)
    x0 += k0; x1 += k1 + 3u;
    TF_RND(17) TF_RND(29) TF_RND(16) TF_RND(24)
    x0 += k1; x1 += k2 + 4u;
    TF_RND(13) TF_RND(15) TF_RND(26) TF_RND(6)
    x0 += k2; x1 += k0 + 5u;
#undef TF_RND
    o0 = x0; o1 = x1;
}

union SmemU {
    struct {
        float planes[2][4][PLSZ];                   // 39168 B
        float wsm[CHPER * 10];                      //  960 B
    } conv;
    struct {
        unsigned long long lists[(KTOP + 1) * 32];  // 5376 B
        int invp[NUNSEL];                           // 4016 B
        int flag[NPIX];                             // 4096 B
        int wc[32];
    } fin;
    uint32_t bits[NUNSEL];                          // perm block
};

__global__ __launch_bounds__(256)
void patch_vote_fused(const float* __restrict__ feature,
                      const float* __restrict__ dww,
                      const float* __restrict__ pww,
                      float* __restrict__ out) {
    __shared__ __align__(16) SmemU sm;
    __shared__ int s_last;
    int tid = threadIdx.x;

    // =========================== permutation blocks ========================
    if (blockIdx.x < NPERMBLK) {
        uint32_t s0, s1;
        threefry2x32(0u, 42u, 0u, 1u, s0, s1);
        for (int i = tid; i < NUNSEL; i += 256) {
            uint32_t b1, b2;
            threefry2x32(s0, s1, 0u, (uint32_t)i, b1, b2);
            sm.bits[i] = b1 ^ b2;        // partitionable 32-bit fold
        }
        __syncthreads();

        int e = tid >> 2, part = tid & 3;
        int idx = blockIdx.x * ELEM_PER_PB + e;
        int rank = 0;
        bool valid = (e < ELEM_PER_PB) && (idx < NUNSEL);
        if (valid) {
            uint32_t bi = sm.bits[idx];
            int q4b = part * 63;
            int q4e = q4b + 63; if (q4e > 251) q4e = 251;
            const uint4* b4 = reinterpret_cast<const uint4*>(sm.bits);
            for (int q4 = q4b; q4 < q4e; q4++) {
                uint4 v = b4[q4];
                int q = q4 * 4;
                rank += (v.x < bi) || (v.x == bi && (q    ) < idx);
                rank += (v.y < bi) || (v.y == bi && (q + 1) < idx);
                rank += (v.z < bi) || (v.z == bi && (q + 2) < idx);
                rank += (v.w < bi) || (v.w == bi && (q + 3) < idx);
            }
        }
        rank += __shfl_xor_sync(0xffffffffu, rank, 1);
        rank += __shfl_xor_sync(0xffffffffu, rank, 2);
        if (valid && part == 0)
            g_invperm[idx] = (rank < NREM) ? rank : -1;
        __threadfence();
        __syncthreads();
        if (tid == 0) {
            int d = atomicAdd(&g_permdone, 1);
            (void)d;
        }
        return;
    }

    // ============================= conv blocks =============================
    int id    = blockIdx.x - NPERMBLK;
    int img   = id >> 4;
    int chunk = id & 15;
    int c0    = chunk * CHPER;

    // halo ring zero (132 cells per plane, 8 planes)
    for (int i = tid; i < 8 * 132; i += 256) {
        int pl = i / 132, r = i - pl * 132;
        int row, col;
        if (r < 34)       { row = 0;             col = r; }
        else if (r < 68)  { row = 33;            col = r - 34; }
        else if (r < 100) { row = 1 + (r - 68);  col = 0; }
        else              { row = 1 + (r - 100); col = 33; }
        (&sm.conv.planes[0][0][0])[pl * PLSZ + row * PLROW + col] = 0.f;
    }
    if (tid < CHPER * 10) {
        int ch = tid / 10, k = tid - ch * 10;
        sm.conv.wsm[tid] = (k < 9) ? __ldg(dww + (size_t)(c0 + ch) * 9 + k)
                                   : __ldg(pww + c0 + ch);
    }

    // 2x2 output tile per thread
    int tx = tid & 15, ty = tid >> 4;
    int px = tx * 2, py = ty * 2;

    // float4 global load -> smem mapping
    int lp = tid * 4;
    int ly = lp >> 5, lx = lp & 31;
    int dstoff = (ly + 1) * PLROW + lx + 1;

    const float4* f4 = reinterpret_cast<const float4*>(
        feature + ((size_t)img * CCH + c0) * NPIX);

    float4 v0, v1, v2, v3;
    v0 = f4[0 * 256 + tid]; v1 = f4[1 * 256 + tid];
    v2 = f4[2 * 256 + tid]; v3 = f4[3 * 256 + tid];
    __syncthreads();            // halo zero + weights complete
    {
        float* d;
        d = &sm.conv.planes[0][0][dstoff]; d[0]=v0.x; d[1]=v0.y; d[2]=v0.z; d[3]=v0.w;
        d = &sm.conv.planes[0][1][dstoff]; d[0]=v1.x; d[1]=v1.y; d[2]=v1.z; d[3]=v1.w;
        d = &sm.conv.planes[0][2][dstoff]; d[0]=v2.x; d[1]=v2.y; d[2]=v2.z; d[3]=v2.w;
        d = &sm.conv.planes[0][3][dstoff]; d[0]=v3.x; d[1]=v3.y; d[2]=v3.z; d[3]=v3.w;
    }
    v0 = f4[4 * 256 + tid]; v1 = f4[5 * 256 + tid];
    v2 = f4[6 * 256 + tid]; v3 = f4[7 * 256 + tid];
    __syncthreads();            // buffer 0 visible to all

    float acc00 = 0.f, acc01 = 0.f, acc10 = 0.f, acc11 = 0.f;

#pragma unroll
    for (int b = 0; b < NBATCH; b++) {
        int cur = b & 1;
        if (b + 1 < NBATCH) {   // store prefetched batch b+1 into other buffer
            float* d;
            d = &sm.conv.planes[cur^1][0][dstoff]; d[0]=v0.x; d[1]=v0.y; d[2]=v0.z; d[3]=v0.w;
            d = &sm.conv.planes[cur^1][1][dstoff]; d[0]=v1.x; d[1]=v1.y; d[2]=v1.z; d[3]=v1.w;
            d = &sm.conv.planes[cur^1][2][dstoff]; d[0]=v2.x; d[1]=v2.y; d[2]=v2.z; d[3]=v2.w;
            d = &sm.conv.planes[cur^1][3][dstoff]; d[0]=v3.x; d[1]=v3.y; d[2]=v3.z; d[3]=v3.w;
        }
        if (b + 2 < NBATCH) {   // prefetch batch b+2 (4 independent LDG.128)
            int cb = (b + 2) * 4;
            v0 = f4[(cb + 0) * 256 + tid]; v1 = f4[(cb + 1) * 256 + tid];
            v2 = f4[(cb + 2) * 256 + tid]; v3 = f4[(cb + 3) * 256 + tid];
        }

#pragma unroll
        for (int j = 0; j < 4; j++) {
            const float* wp = sm.conv.wsm + (b * 4 + j) * 10;
            float w0 = wp[0], w1 = wp[1], w2 = wp[2];
            float w3 = wp[3], w4 = wp[4], w5 = wp[5];
            float w6 = wp[6], w7 = wp[7], w8 = wp[8];
            float pwc = wp[9];

            const float2* p2 = reinterpret_cast<const float2*>(
                &sm.conv.planes[cur][j][py * PLROW + px]);
            float2 q00 = p2[0],  q01 = p2[1];
            float2 q10 = p2[18], q11 = p2[19];
            float2 q20 = p2[36], q21 = p2[37];
            float2 q30 = p2[54], q31 = p2[55];
            float a00=q00.x, a01=q00.y, a02=q01.x, a03=q01.y;
            float a10=q10.x, a11=q10.y, a12=q11.x, a13=q11.y;
            float a20=q20.x, a21=q20.y, a22=q21.x, a23=q21.y;
            float a30=q30.x, a31=q30.y, a32=q31.x, a33=q31.y;

            float s00 = w0*a00 + w1*a01 + w2*a02
                      + w3*a10 + w4*a11 + w5*a12
                      + w6*a20 + w7*a21 + w8*a22;
            float s01 = w0*a01 + w1*a02 + w2*a03
                      + w3*a11 + w4*a12 + w5*a13
                      + w6*a21 + w7*a22 + w8*a23;
            float s10 = w0*a10 + w1*a11 + w2*a12
                      + w3*a20 + w4*a21 + w5*a22
                      + w6*a30 + w7*a31 + w8*a32;
            float s11 = w0*a11 + w1*a12 + w2*a13
                      + w3*a21 + w4*a22 + w5*a23
                      + w6*a31 + w7*a32 + w8*a33;

            acc00 = fmaf(pwc, s00, acc00);
            acc01 = fmaf(pwc, s01, acc01);
            acc10 = fmaf(pwc, s10, acc10);
            acc11 = fmaf(pwc, s11, acc11);
        }
        __syncthreads();        // everyone done with planes[cur] & stores
    }

    // write this block's slice
    {
        float2* o2 = reinterpret_cast<float2*>(
            g_partial + ((size_t)img * NCHUNK + chunk) * NPIX);
        float2 r0; r0.x = acc00; r0.y = acc01;
        float2 r1; r1.x = acc10; r1.y = acc11;
        o2[(py * 32 + px) >> 1]       = r0;
        o2[((py + 1) * 32 + px) >> 1] = r1;
    }

    // last-block election (threadFenceReduction pattern)
    __threadfence();
    __syncthreads();
    if (tid == 0) {
        int old = atomicAdd(&g_cnt[img], 1);
        s_last = (old == NCHUNK - 1) ? 1 : 0;
    }
    __syncthreads();
    if (!s_last) return;

    // ====================== finalize (256 threads, 4 passes) ===============
    int lane = tid & 31, warp = tid >> 5;

    // wait for all 16 permutation blocks (all blocks co-resident: safe spin)
    if (tid == 0) {
        while (atomicAdd(&g_permdone, 0) < NPERMBLK) {}
    }
    __syncthreads();

#pragma unroll
    for (int p = 0; p < NPASS; p++) {
        sm.fin.flag[p * 256 + tid] = 0;
        if (p * 256 + tid < NUNSEL)
            sm.fin.invp[p * 256 + tid] = g_invperm[p * 256 + tid];
    }

    // deterministic slice reduction for 4 pixels (64 independent loads)
    unsigned long long key[NPASS];
#pragma unroll
    for (int p = 0; p < NPASS; p++) {
        int pix = p * 256 + tid;
        const float* pp = g_partial + (size_t)img * NCHUNK * NPIX + pix;
        float a[NCHUNK];
#pragma unroll
        for (int c = 0; c < NCHUNK; c++)
            a[c] = __ldg(pp + (size_t)c * NPIX);
#pragma unroll
        for (int st = 1; st < NCHUNK; st <<= 1)
#pragma unroll
            for (int c = 0; c < NCHUNK; c += 2 * st)
                a[c] += a[c + st];
        uint32_t fb = __float_as_uint(a[0]);
        fb = (fb & 0x80000000u) ? ~fb : (fb | 0x80000000u);
        key[p] = ((unsigned long long)fb << 32) | (uint32_t)(NPIX - 1 - pix);
    }

    // 4 interleaved per-warp bitonic sorts, DESCENDING (ILP across passes)
#pragma unroll
    for (int k = 2; k <= 32; k <<= 1) {
#pragma unroll
        for (int j = k >> 1; j > 0; j >>= 1) {
            bool dirAsc  = ((lane & k) != 0);
            bool isLower = ((lane & j) == 0);
            bool takeMin = (dirAsc == isLower);
#pragma unroll
            for (int p = 0; p < NPASS; p++) {
                unsigned long long o = __shfl_xor_sync(0xffffffffu, key[p], j);
                key[p] = takeMin ? (key[p] < o ? key[p] : o)
                                 : (key[p] > o ? key[p] : o);
            }
        }
    }
    // 32 sorted lists: list index = p*8 + warp; row 20 = sentinel zeros
    if (lane <= KTOP) {
#pragma unroll
        for (int p = 0; p < NPASS; p++)
            sm.fin.lists[lane * 32 + (p * 8 + warp)] =
                (lane < KTOP) ? key[p] : 0ull;
    }
    __syncthreads();

    // exact 32-way tournament merge on warp 0, REDUX-based rounds
    if (warp == 0) {
        int h = 0;
        unsigned long long head = sm.fin.lists[lane];
        for (int r = 0; r < KTOP; r++) {
            uint32_t hi = (uint32_t)(head >> 32);
            uint32_t lo = (uint32_t)head;
            uint32_t m1 = __reduce_max_sync(0xffffffffu, hi);
            uint32_t lo2 = (hi == m1) ? lo : 0u;
            uint32_t m2 = __reduce_max_sync(0xffffffffu, lo2);
            if (hi == m1 && lo == m2) {             // unique winner
                int pix = NPIX - 1 - (int)(lo & 1023u);
                int X = pix & 31, Y = pix >> 5;
                out[              img * PTOT + r] = (float)(X < 1 ? 1 : X);
                out[NIMG * PTOT + img * PTOT + r] = (float)(Y < 1 ? 1 : Y);
                sm.fin.flag[pix] = 1;
                h++;
                head = sm.fin.lists[h * 32 + lane]; // row 20 = sentinel
            }
        }
    }
    __syncthreads();

    // unselected positions: per-pass ballots + scan over 32 (pass,warp) counts
    unsigned bal[NPASS];
#pragma unroll
    for (int p = 0; p < NPASS; p++) {
        bool sel = (sm.fin.flag[p * 256 + tid] != 0);
        bal[p] = __ballot_sync(0xffffffffu, sel);
        if (lane == 0) sm.fin.wc[p * 8 + warp] = __popc(bal[p]);
    }
    __syncthreads();
    if (warp == 0) {
        int v = sm.fin.wc[lane], sc = v;
#pragma unroll
        for (int off = 1; off < 32; off <<= 1) {
            int o = __shfl_up_sync(0xffffffffu, sc, off);
            if (lane >= off) sc += o;
        }
        sm.fin.wc[lane] = sc - v;     // exclusive prefix over pixel order
    }
    __syncthreads();

#pragma unroll
    for (int p = 0; p < NPASS; p++) {
        int pix = p * 256 + tid;
        bool sel = (sm.fin.flag[pix] != 0);
        int before = sm.fin.wc[p * 8 + warp]
                   + __popc(bal[p] & ((1u << lane) - 1u));
        if (!sel) {
            int u = pix - before;         // position among unselected
            int j = sm.fin.invp[u];
            if (j >= 0) {
                int X = pix & 31, Y = pix >> 5;
                out[              img * PTOT + KTOP + j] = (float)(X < 1 ? 1 : X);
                out[NIMG * PTOT + img * PTOT + KTOP + j] = (float)(Y < 1 ? 1 : Y);
            }
        }
    }

    // counter resets for graph replay
    __syncthreads();
    if (tid == 0) {
        atomicExch(&g_cnt[img], 0);
        int f = atomicAdd(&g_findone, 1);
        if (f == NIMG - 1) {
            atomicExch(&g_permdone, 0);
            atomicExch(&g_findone, 0);
        }
    }
}

extern "C" void kernel_launch(void* const* d_in, const int* in_sizes, int n_in,
                              void* d_out, int out_size) {
    const float* feature = (const float*)d_in[0];
    const float* dww     = (const float*)d_in[1];
    const float* pww     = (const float*)d_in[3];
    float* out = (float*)d_out;

    patch_vote_fused<<<NPERMBLK + NIMG * NCHUNK, 256>>>(feature, dww, pww, out);
}

// round 10
// speedup vs baseline: 2.3704x; 1.0148x over previous
#include <cuda_runtime.h>
#include <cstdint>

// Problem constants
#define CCH    384
#define NPIX   1024          // 32*32
#define NIMG   16            // only first n=16 rows matter
#define KTOP   20
#define PTOT   96
#define NREM   76            // P - K
#define NUNSEL 1004          // 1024 - 20
#define NCHUNK 32            // conv blocks per image
#define CHPER  12            // 384 / 32
#define NBATCH 3             // 12 channels / 4 planes per batch
#define NPERMBLK 16
#define ELEM_PER_PB 63       // 16*63 = 1008 >= 1004
#define PLROW  36            // padded row -> aligned float2 reads
#define PLSZ   (PLROW * 34)

// Scratch (device globals: no allocation allowed)
__device__ float g_partial[NCHUNK * NIMG * NPIX];   // [chunk][img][pix]
__device__ int   g_invperm[NUNSEL];

__device__ __forceinline__ uint32_t rotl32(uint32_t x, int d) {
    return (x << d) | (x >> (32 - d));
}

// Threefry-2x32, 20 rounds (matches JAX threefry2x32_p)
__device__ __forceinline__ void threefry2x32(uint32_t k0, uint32_t k1,
                                             uint32_t x0, uint32_t x1,
                                             uint32_t& o0, uint32_t& o1) {
    uint32_t k2 = k0 ^ k1 ^ 0x1BD11BDAu;
#define TF_RND(r) { x0 += x1; x1 = rotl32(x1, (r)); x1 ^= x0; }
    x0 += k0; x1 += k1;
    TF_RND(13) TF_RND(15) TF_RND(26) TF_RND(6)
    x0 += k1; x1 += k2 + 1u;
    TF_RND(17) TF_RND(29) TF_RND(16) TF_RND(24)
    x0 += k2; x1 += k0 + 2u;
    TF_RND(13) TF_RND(15) TF_RND(26) TF_RND(6)
    x0 += k0; x1 += k1 + 3u;
    TF_RND(17) TF_RND(29) TF_RND(16) TF_RND(24)
    x0 += k1; x1 += k2 + 4u;
    TF_RND(13) TF_RND(15) TF_RND(26) TF_RND(6)
    x0 += k2; x1 += k0 + 5u;
#undef TF_RND
    o0 = x0; o1 = x1;
}

// ---------------------------------------------------------------------------
// Kernel A: blocks [0,16): JAX permutation inverse map.
//           blocks [16, 16+512): fused depthwise-3x3 + pointwise partials,
//           12 channels/block (3 batches of 4 planes, double-buffered,
//           MLP=4 prefetch), 512 conv blocks -> ~3.6 CTAs/SM.
// ---------------------------------------------------------------------------
__global__ __launch_bounds__(256)
void patch_vote_kA(const float* __restrict__ feature,
                   const float* __restrict__ dww,
                   const float* __restrict__ pww) {
    int tid = threadIdx.x;

    if (blockIdx.x < NPERMBLK) {
        // ---- permutation block (verified exact) ----
        __shared__ __align__(16) uint32_t bits[NUNSEL];   // 1004 = 251 * 4
        uint32_t s0, s1;
        threefry2x32(0u, 42u, 0u, 1u, s0, s1);
        for (int i = tid; i < NUNSEL; i += 256) {
            uint32_t b1, b2;
            threefry2x32(s0, s1, 0u, (uint32_t)i, b1, b2);
            bits[i] = b1 ^ b2;
        }
        __syncthreads();

        int e = tid >> 2, part = tid & 3;
        int idx = blockIdx.x * ELEM_PER_PB + e;
        int rank = 0;
        bool valid = (e < ELEM_PER_PB) && (idx < NUNSEL);
        if (valid) {
            uint32_t bi = bits[idx];
            int q4b = part * 63;
            int q4e = q4b + 63; if (q4e > 251) q4e = 251;
            const uint4* b4 = reinterpret_cast<const uint4*>(bits);
            for (int q4 = q4b; q4 < q4e; q4++) {
                uint4 v = b4[q4];
                int q = q4 * 4;
                rank += (v.x < bi) || (v.x == bi && (q    ) < idx);
                rank += (v.y < bi) || (v.y == bi && (q + 1) < idx);
                rank += (v.z < bi) || (v.z == bi && (q + 2) < idx);
                rank += (v.w < bi) || (v.w == bi && (q + 3) < idx);
            }
        }
        rank += __shfl_xor_sync(0xffffffffu, rank, 1);
        rank += __shfl_xor_sync(0xffffffffu, rank, 2);
        if (valid && part == 0)
            g_invperm[idx] = (rank < NREM) ? rank : -1;
        return;
    }

    // ---- conv block ----
    int id    = blockIdx.x - NPERMBLK;
    int img   = id >> 5;          // / NCHUNK
    int chunk = id & 31;
    int c0    = chunk * CHPER;

    __shared__ __align__(16) float planes[2][4][PLSZ];
    __shared__ float wsm[CHPER * 10];

    // zero only the halo ring (132 cells) of each of the 8 planes
    for (int i = tid; i < 8 * 132; i += 256) {
        int pl = i / 132, r = i - pl * 132;
        int row, col;
        if (r < 34)       { row = 0;             col = r; }
        else if (r < 68)  { row = 33;            col = r - 34; }
        else if (r < 100) { row = 1 + (r - 68);  col = 0; }
        else              { row = 1 + (r - 100); col = 33; }
        (&planes[0][0][0])[pl * PLSZ + row * PLROW + col] = 0.f;
    }
    if (tid < CHPER * 10) {
        int ch = tid / 10, k = tid - ch * 10;
        wsm[tid] = (k < 9) ? __ldg(dww + (size_t)(c0 + ch) * 9 + k)
                           : __ldg(pww + c0 + ch);
    }

    // 2x2 output tile per thread
    int tx = tid & 15, ty = tid >> 4;
    int px = tx * 2, py = ty * 2;

    // float4 global load -> smem mapping
    int lp = tid * 4;
    int ly = lp >> 5, lx = lp & 31;
    int dstoff = (ly + 1) * PLROW + lx + 1;

    const float4* f4 = reinterpret_cast<const float4*>(
        feature + ((size_t)img * CCH + c0) * NPIX);

    float4 v0, v1, v2, v3;
    v0 = f4[0 * 256 + tid]; v1 = f4[1 * 256 + tid];
    v2 = f4[2 * 256 + tid]; v3 = f4[3 * 256 + tid];
    __syncthreads();            // halo zero + weights complete
    {
        float* d;
        d = &planes[0][0][dstoff]; d[0]=v0.x; d[1]=v0.y; d[2]=v0.z; d[3]=v0.w;
        d = &planes[0][1][dstoff]; d[0]=v1.x; d[1]=v1.y; d[2]=v1.z; d[3]=v1.w;
        d = &planes[0][2][dstoff]; d[0]=v2.x; d[1]=v2.y; d[2]=v2.z; d[3]=v2.w;
        d = &planes[0][3][dstoff]; d[0]=v3.x; d[1]=v3.y; d[2]=v3.z; d[3]=v3.w;
    }
    v0 = f4[4 * 256 + tid]; v1 = f4[5 * 256 + tid];
    v2 = f4[6 * 256 + tid]; v3 = f4[7 * 256 + tid];
    __syncthreads();            // buffer 0 visible to all

    float acc00 = 0.f, acc01 = 0.f, acc10 = 0.f, acc11 = 0.f;

#pragma unroll
    for (int b = 0; b < NBATCH; b++) {
        int cur = b & 1;
        if (b + 1 < NBATCH) {   // store prefetched batch b+1 into other buffer
            float* d;
            d = &planes[cur^1][0][dstoff]; d[0]=v0.x; d[1]=v0.y; d[2]=v0.z; d[3]=v0.w;
            d = &planes[cur^1][1][dstoff]; d[0]=v1.x; d[1]=v1.y; d[2]=v1.z; d[3]=v1.w;
            d = &planes[cur^1][2][dstoff]; d[0]=v2.x; d[1]=v2.y; d[2]=v2.z; d[3]=v2.w;
            d = &planes[cur^1][3][dstoff]; d[0]=v3.x; d[1]=v3.y; d[2]=v3.z; d[3]=v3.w;
        }
        if (b + 2 < NBATCH) {   // prefetch batch b+2 (4 independent LDG.128)
            int cb = (b + 2) * 4;
            v0 = f4[(cb + 0) * 256 + tid]; v1 = f4[(cb + 1) * 256 + tid];
            v2 = f4[(cb + 2) * 256 + tid]; v3 = f4[(cb + 3) * 256 + tid];
        }

#pragma unroll
        for (int j = 0; j < 4; j++) {
            const float* wp = wsm + (b * 4 + j) * 10;
            float w0 = wp[0], w1 = wp[1], w2 = wp[2];
            float w3 = wp[3], w4 = wp[4], w5 = wp[5];
            float w6 = wp[6], w7 = wp[7], w8 = wp[8];
            float pwc = wp[9];

            // 4x4 patch via 8 aligned float2 loads
            const float2* p2 = reinterpret_cast<const float2*>(
                &planes[cur][j][py * PLROW + px]);
            float2 q00 = p2[0],  q01 = p2[1];
            float2 q10 = p2[18], q11 = p2[19];
            float2 q20 = p2[36], q21 = p2[37];
            float2 q30 = p2[54], q31 = p2[55];
            float a00=q00.x, a01=q00.y, a02=q01.x, a03=q01.y;
            float a10=q10.x, a11=q10.y, a12=q11.x, a13=q11.y;
            float a20=q20.x, a21=q20.y, a22=q21.x, a23=q21.y;
            float a30=q30.x, a31=q30.y, a32=q31.x, a33=q31.y;

            float s00 = w0*a00 + w1*a01 + w2*a02
                      + w3*a10 + w4*a11 + w5*a12
                      + w6*a20 + w7*a21 + w8*a22;
            float s01 = w0*a01 + w1*a02 + w2*a03
                      + w3*a11 + w4*a12 + w5*a13
                      + w6*a21 + w7*a22 + w8*a23;
            float s10 = w0*a10 + w1*a11 + w2*a12
                      + w3*a20 + w4*a21 + w5*a22
                      + w6*a30 + w7*a31 + w8*a32;
            float s11 = w0*a11 + w1*a12 + w2*a13
                      + w3*a21 + w4*a22 + w5*a23
                      + w6*a31 + w7*a32 + w8*a33;

            acc00 = fmaf(pwc, s00, acc00);
            acc01 = fmaf(pwc, s01, acc01);
            acc10 = fmaf(pwc, s10, acc10);
            acc11 = fmaf(pwc, s11, acc11);
        }
        __syncthreads();        // everyone done with planes[cur] & stores
    }

    float2* o2 = reinterpret_cast<float2*>(
        g_partial + (size_t)(chunk * NIMG + img) * NPIX);
    float2 r0; r0.x = acc00; r0.y = acc01;
    float2 r1; r1.x = acc10; r1.y = acc11;
    o2[(py * 32 + px) >> 1]       = r0;
    o2[((py + 1) * 32 + px) >> 1] = r1;
}

// ---------------------------------------------------------------------------
// Kernel B: full-MLP 32-slice tree reduce, per-warp bitonic sort, exact
//           32-way tournament merge with REDUX max, scan-based unselected
//           prefix, invperm gather, float32 outputs.
// ---------------------------------------------------------------------------
__global__ __launch_bounds__(1024)
void patch_vote_kB(float* __restrict__ out) {
    int tid  = threadIdx.x;
    int img  = blockIdx.x;
    int lane = tid & 31, warp = tid >> 5;

    __shared__ unsigned long long s_lists[(KTOP + 1) * 32];  // [rank][warp]
    __shared__ int s_invp[NUNSEL];
    __shared__ int s_flag[NPIX];
    __shared__ int warpcnt[32];

    if (tid < NUNSEL) s_invp[tid] = g_invperm[tid];
    s_flag[tid] = 0;

    // chunk reduction: 32 fully independent loads, pairwise tree sum
    const float* pp = g_partial + (size_t)img * NPIX + tid;
    float a[NCHUNK];
#pragma unroll
    for (int c = 0; c < NCHUNK; c++)
        a[c] = __ldg(pp + (size_t)c * NIMG * NPIX);
#pragma unroll
    for (int s = 1; s < NCHUNK; s <<= 1)
#pragma unroll
        for (int c = 0; c < NCHUNK; c += 2 * s)
            a[c] += a[c + s];
    float val = a[0];

    // orderable key: (monotone float bits : 1023 - pix) -> max == JAX order
    uint32_t fb = __float_as_uint(val);
    fb = (fb & 0x80000000u) ? ~fb : (fb | 0x80000000u);
    unsigned long long key =
        ((unsigned long long)fb << 32) | (uint32_t)(NPIX - 1 - tid);

    // per-warp bitonic sort, DESCENDING (lane 0 = max). Keys unique.
#pragma unroll
    for (int k = 2; k <= 32; k <<= 1) {
#pragma unroll
        for (int j = k >> 1; j > 0; j >>= 1) {
            unsigned long long o = __shfl_xor_sync(0xffffffffu, key, j);
            bool dirAsc  = ((lane & k) != 0);
            bool isLower = ((lane & j) == 0);
            bool takeMin = (dirAsc == isLower);
            key = takeMin ? (key < o ? key : o) : (key > o ? key : o);
        }
    }
    // store sorted top-20 column-major; row 20 = sentinel zeros
    if (lane <= KTOP)
        s_lists[lane * 32 + warp] = (lane < KTOP) ? key : 0ull;
    __syncthreads();

    // exact 32-way tournament merge on warp 0, REDUX-based rounds
    if (warp == 0) {
        int h = 0;
        unsigned long long head = s_lists[lane];   // head of list `lane`
        for (int r = 0; r < KTOP; r++) {
            uint32_t hi = (uint32_t)(head >> 32);
            uint32_t lo = (uint32_t)head;
            uint32_t m1 = __reduce_max_sync(0xffffffffu, hi);
            uint32_t lo2 = (hi == m1) ? lo : 0u;
            uint32_t m2 = __reduce_max_sync(0xffffffffu, lo2);
            if (hi == m1 && lo == m2) {            // unique winner
                int pix = NPIX - 1 - (int)(lo & 1023u);
                int X = pix & 31, Y = pix >> 5;
                out[              img * PTOT + r] = (float)(X < 1 ? 1 : X);
                out[NIMG * PTOT + img * PTOT + r] = (float)(Y < 1 ? 1 : Y);
                s_flag[pix] = 1;
                h++;
                head = s_lists[h * 32 + lane];     // h <= 20 -> sentinel row
            }
        }
    }
    __syncthreads();

    // unselected positions via ballot + warp-0 scan of warp counts
    bool sel = (s_flag[tid] != 0);
    unsigned bal = __ballot_sync(0xffffffffu, sel);
    if (lane == 0) warpcnt[warp] = __popc(bal);
    __syncthreads();
    if (warp == 0) {
        int v = warpcnt[lane], s = v;
#pragma unroll
        for (int off = 1; off < 32; off <<= 1) {
            int o = __shfl_up_sync(0xffffffffu, s, off);
            if (lane >= off) s += o;
        }
        warpcnt[lane] = s - v;      // exclusive prefix
    }
    __syncthreads();
    int before = warpcnt[warp] + __popc(bal & ((1u << lane) - 1u));

    if (!sel) {
        int u = tid - before;           // position among unselected (0..1003)
        int j = s_invp[u];
        if (j >= 0) {
            int X = tid & 31, Y = tid >> 5;
            out[              img * PTOT + KTOP + j] = (float)(X < 1 ? 1 : X);
            out[NIMG * PTOT + img * PTOT + KTOP + j] = (float)(Y < 1 ? 1 : Y);
        }
    }
}

extern "C" void kernel_launch(void* const* d_in, const int* in_sizes, int n_in,
                              void* d_out, int out_size) {
    const float* feature = (const float*)d_in[0];
    const float* dww     = (const float*)d_in[1];
    const float* pww     = (const float*)d_in[3];
    float* out = (float*)d_out;

    patch_vote_kA<<<NPERMBLK + NCHUNK * NIMG, 256>>>(feature, dww, pww);
    patch_vote_kB<<<NIMG, 1024>>>(out);
}

// round 11
// speedup vs baseline: 2.7730x; 1.1698x over previous
#include <cuda_runtime.h>
#include <cstdint>

// Problem constants
#define CCH    384
#define NPIX   1024          // 32*32
#define NIMG   16            // only first n=16 rows matter
#define KTOP   20
#define PTOT   96
#define NREM   76            // P - K
#define NUNSEL 1004          // 1024 - 20
#define NCHUNK 16            // conv blocks per image
#define CHPER  24            // 384 / 16
#define NBATCH 6             // 24 channels / 4 planes per batch
#define NPERMBLK 16
#define ELEM_PER_PB 63       // 16*63 = 1008 >= 1004
#define PLROW  36            // padded row -> 16B-aligned 4-col reads
#define PLSZ   (PLROW * 34)

typedef unsigned long long u64;

// Scratch (device globals: no allocation allowed)
__device__ float g_partial[NCHUNK * NIMG * NPIX];   // [chunk][img][pix]
__device__ int   g_invperm[NUNSEL];

__device__ __forceinline__ uint32_t rotl32(uint32_t x, int d) {
    return (x << d) | (x >> (32 - d));
}

// packed f32x2 helpers (sm_100+)
__device__ __forceinline__ u64 pk2(float lo, float hi) {
    u64 r; asm("mov.b64 %0,{%1,%2};" : "=l"(r) : "f"(lo), "f"(hi)); return r;
}
__device__ __forceinline__ u64 fma2(u64 a, u64 b, u64 c) {
    u64 d; asm("fma.rn.f32x2 %0,%1,%2,%3;" : "=l"(d) : "l"(a), "l"(b), "l"(c));
    return d;
}
__device__ __forceinline__ u64 add2(u64 a, u64 b) {
    u64 d; asm("add.rn.f32x2 %0,%1,%2;" : "=l"(d) : "l"(a), "l"(b)); return d;
}
__device__ __forceinline__ float2 upk2(u64 a) {
    float2 f; asm("mov.b64 {%0,%1},%2;" : "=f"(f.x), "=f"(f.y) : "l"(a));
    return f;
}

// Threefry-2x32, 20 rounds (matches JAX threefry2x32_p)
__device__ __forceinline__ void threefry2x32(uint32_t k0, uint32_t k1,
                                             uint32_t x0, uint32_t x1,
                                             uint32_t& o0, uint32_t& o1) {
    uint32_t k2 = k0 ^ k1 ^ 0x1BD11BDAu;
#define TF_RND(r) { x0 += x1; x1 = rotl32(x1, (r)); x1 ^= x0; }
    x0 += k0; x1 += k1;
    TF_RND(13) TF_RND(15) TF_RND(26) TF_RND(6)
    x0 += k1; x1 += k2 + 1u;
    TF_RND(17) TF_RND(29) TF_RND(16) TF_RND(24)
    x0 += k2; x1 += k0 + 2u;
    TF_RND(13) TF_RND(15) TF_RND(26) TF_RND(6)
    x0 += k0; x1 += k1 + 3u;
    TF_RND(17) TF_RND(29) TF_RND(16) TF_RND(24)
    x0 += k1; x1 += k2 + 4u;
    TF_RND(13) TF_RND(15) TF_RND(26) TF_RND(6)
    x0 += k2; x1 += k0 + 5u;
#undef TF_RND
    o0 = x0; o1 = x1;
}

// ---------------------------------------------------------------------------
// Kernel A: blocks [0,16): JAX permutation inverse map.
//           blocks [16, 16+256): fused depthwise-3x3 + pointwise partials.
//           R7 skeleton (24 ch, double-buffered 4-plane batches, MLP=4
//           prefetch, 1 barrier/batch); NEW compute: 64 threads/plane with
//           4x4 tiles + packed f32x2 FMA; cross-plane reduce at end.
// ---------------------------------------------------------------------------
__global__ __launch_bounds__(256)
void patch_vote_kA(const float* __restrict__ feature,
                   const float* __restrict__ dww,
                   const float* __restrict__ pww) {
    int tid = threadIdx.x;

    if (blockIdx.x < NPERMBLK) {
        // ---- permutation block (verified exact) ----
        __shared__ __align__(16) uint32_t bits[NUNSEL];   // 1004 = 251 * 4
        uint32_t s0, s1;
        threefry2x32(0u, 42u, 0u, 1u, s0, s1);
        for (int i = tid; i < NUNSEL; i += 256) {
            uint32_t b1, b2;
            threefry2x32(s0, s1, 0u, (uint32_t)i, b1, b2);
            bits[i] = b1 ^ b2;
        }
        __syncthreads();

        int e = tid >> 2, part = tid & 3;
        int idx = blockIdx.x * ELEM_PER_PB + e;
        int rank = 0;
        bool valid = (e < ELEM_PER_PB) && (idx < NUNSEL);
        if (valid) {
            uint32_t bi = bits[idx];
            int q4b = part * 63;
            int q4e = q4b + 63; if (q4e > 251) q4e = 251;
            const uint4* b4 = reinterpret_cast<const uint4*>(bits);
            for (int q4 = q4b; q4 < q4e; q4++) {
                uint4 v = b4[q4];
                int q = q4 * 4;
                rank += (v.x < bi) || (v.x == bi && (q    ) < idx);
                rank += (v.y < bi) || (v.y == bi && (q + 1) < idx);
                rank += (v.z < bi) || (v.z == bi && (q + 2) < idx);
                rank += (v.w < bi) || (v.w == bi && (q + 3) < idx);
            }
        }
        rank += __shfl_xor_sync(0xffffffffu, rank, 1);
        rank += __shfl_xor_sync(0xffffffffu, rank, 2);
        if (valid && part == 0)
            g_invperm[idx] = (rank < NREM) ? rank : -1;
        return;
    }

    // ---- conv block ----
    int id    = blockIdx.x - NPERMBLK;
    int img   = id >> 4;          // / NCHUNK
    int chunk = id & 15;
    int c0    = chunk * CHPER;

    __shared__ __align__(16) float planes[2][4][PLSZ];
    __shared__ __align__(8) float2 wsm2[CHPER * 9];   // (pw*w, pw*w) pairs

    // zero only the halo ring (132 cells) of each of the 8 planes
    for (int i = tid; i < 8 * 132; i += 256) {
        int pl = i / 132, r = i - pl * 132;
        int row, col;
        if (r < 34)       { row = 0;             col = r; }
        else if (r < 68)  { row = 33;            col = r - 34; }
        else if (r < 100) { row = 1 + (r - 68);  col = 0; }
        else              { row = 1 + (r - 100); col = 33; }
        (&planes[0][0][0])[pl * PLSZ + row * PLROW + col] = 0.f;
    }
    if (tid < CHPER * 9) {
        int ch = tid / 9, k = tid - ch * 9;
        float v = __ldg(dww + (size_t)(c0 + ch) * 9 + k) * __ldg(pww + c0 + ch);
        wsm2[tid] = make_float2(v, v);
    }

    // compute mapping: plane j = tid>>6; 4x4 tile within plane
    int j  = tid >> 6;
    int s  = tid & 63;
    int tx = s & 7, ty = s >> 3;
    int R = ty * 4, C = tx * 4;   // output tile origin (= plane patch origin)

    // float4 global load -> smem mapping (unchanged from R7)
    int lp = tid * 4;
    int ly = lp >> 5, lx = lp & 31;
    int dstoff = (ly + 1) * PLROW + lx + 1;

    const float4* f4 = reinterpret_cast<const float4*>(
        feature + ((size_t)img * CCH + c0) * NPIX);

    float4 v0, v1, v2, v3;
    v0 = f4[0 * 256 + tid]; v1 = f4[1 * 256 + tid];
    v2 = f4[2 * 256 + tid]; v3 = f4[3 * 256 + tid];
    __syncthreads();            // halo zero + weights complete
    {
        float* d;
        d = &planes[0][0][dstoff]; d[0]=v0.x; d[1]=v0.y; d[2]=v0.z; d[3]=v0.w;
        d = &planes[0][1][dstoff]; d[0]=v1.x; d[1]=v1.y; d[2]=v1.z; d[3]=v1.w;
        d = &planes[0][2][dstoff]; d[0]=v2.x; d[1]=v2.y; d[2]=v2.z; d[3]=v2.w;
        d = &planes[0][3][dstoff]; d[0]=v3.x; d[1]=v3.y; d[2]=v3.z; d[3]=v3.w;
    }
    v0 = f4[4 * 256 + tid]; v1 = f4[5 * 256 + tid];
    v2 = f4[6 * 256 + tid]; v3 = f4[7 * 256 + tid];
    __syncthreads();            // buffer 0 visible to all

    u64 aL[4] = {0ull, 0ull, 0ull, 0ull};   // packed (col 0,1) accumulators
    u64 aR[4] = {0ull, 0ull, 0ull, 0ull};   // packed (col 2,3) accumulators

#pragma unroll
    for (int b = 0; b < NBATCH; b++) {
        int cur = b & 1;
        if (b + 1 < NBATCH) {   // store prefetched batch b+1 into other buffer
            float* d;
            d = &planes[cur^1][0][dstoff]; d[0]=v0.x; d[1]=v0.y; d[2]=v0.z; d[3]=v0.w;
            d = &planes[cur^1][1][dstoff]; d[0]=v1.x; d[1]=v1.y; d[2]=v1.z; d[3]=v1.w;
            d = &planes[cur^1][2][dstoff]; d[0]=v2.x; d[1]=v2.y; d[2]=v2.z; d[3]=v2.w;
            d = &planes[cur^1][3][dstoff]; d[0]=v3.x; d[1]=v3.y; d[2]=v3.z; d[3]=v3.w;
        }
        if (b + 2 < NBATCH) {   // prefetch batch b+2 (4 independent LDG.128)
            int cb = (b + 2) * 4;
            v0 = f4[(cb + 0) * 256 + tid]; v1 = f4[(cb + 1) * 256 + tid];
            v2 = f4[(cb + 2) * 256 + tid]; v3 = f4[(cb + 3) * 256 + tid];
        }

        // this thread's channel for this batch: b*4 + j (plane j)
        const u64* wq = reinterpret_cast<const u64*>(wsm2 + (b * 4 + j) * 9);
        u64 W0 = wq[0], W1 = wq[1], W2 = wq[2];
        u64 W3 = wq[3], W4 = wq[4], W5 = wq[5];
        u64 W6 = wq[6], W7 = wq[7], W8 = wq[8];

        const float* pb = &planes[cur][j][R * PLROW + C];
#pragma unroll
        for (int r = 0; r < 6; r++) {
            float4 q0 = *reinterpret_cast<const float4*>(pb + r * PLROW);
            float2 q1 = *reinterpret_cast<const float2*>(pb + r * PLROW + 4);
            u64 P0 = pk2(q0.x, q0.y);
            u64 P1 = pk2(q0.y, q0.z);
            u64 P2 = pk2(q0.z, q0.w);
            u64 P3 = pk2(q0.w, q1.x);
            u64 P4 = pk2(q1.x, q1.y);
#pragma unroll
            for (int w = 0; w < 3; w++) {
                int o = r - w;
                if (o >= 0 && o <= 3) {
                    u64 Wa = (w == 0) ? W0 : (w == 1) ? W3 : W6;
                    u64 Wb = (w == 0) ? W1 : (w == 1) ? W4 : W7;
                    u64 Wc = (w == 0) ? W2 : (w == 1) ? W5 : W8;
                    aL[o] = fma2(Wa, P0, aL[o]);
                    aL[o] = fma2(Wb, P1, aL[o]);
                    aL[o] = fma2(Wc, P2, aL[o]);
                    aR[o] = fma2(Wa, P2, aR[o]);
                    aR[o] = fma2(Wb, P3, aR[o]);
                    aR[o] = fma2(Wc, P4, aR[o]);
                }
            }
        }
        __syncthreads();        // everyone done with planes[cur] & stores
    }

    // cross-plane reduction: planes smem is dead now; reuse as scratch.
    u64* red = reinterpret_cast<u64*>(&planes[0][0][0]);
    if (j != 0) {
        u64* dst = red + ((j - 1) * 64 + s) * 8;
#pragma unroll
        for (int o = 0; o < 4; o++) { dst[o] = aL[o]; dst[4 + o] = aR[o]; }
    }
    __syncthreads();
    if (j == 0) {
#pragma unroll
        for (int jj = 0; jj < 3; jj++) {
            const u64* src = red + (jj * 64 + s) * 8;
#pragma unroll
            for (int o = 0; o < 4; o++) {
                aL[o] = add2(aL[o], src[o]);
                aR[o] = add2(aR[o], src[4 + o]);
            }
        }
        float* outp = g_partial + (size_t)(chunk * NIMG + img) * NPIX;
#pragma unroll
        for (int o = 0; o < 4; o++) {
            float2 l = upk2(aL[o]), rr = upk2(aR[o]);
            float4 v; v.x = l.x; v.y = l.y; v.z = rr.x; v.w = rr.y;
            *reinterpret_cast<float4*>(outp + (R + o) * 32 + C) = v;
        }
    }
}

// ---------------------------------------------------------------------------
// Kernel B (R7 verbatim): full-MLP chunk reduce, per-warp bitonic sort,
//           exact 32-way tournament merge with REDUX max, scan-based
//           unselected prefix, invperm gather, float32 outputs.
// ---------------------------------------------------------------------------
__global__ __launch_bounds__(1024)
void patch_vote_kB(float* __restrict__ out) {
    int tid  = threadIdx.x;
    int img  = blockIdx.x;
    int lane = tid & 31, warp = tid >> 5;

    __shared__ unsigned long long s_lists[(KTOP + 1) * 32];  // [rank][warp]
    __shared__ int s_invp[NUNSEL];
    __shared__ int s_flag[NPIX];
    __shared__ int warpcnt[32];

    if (tid < NUNSEL) s_invp[tid] = g_invperm[tid];
    s_flag[tid] = 0;

    // chunk reduction: 16 fully independent loads, pairwise tree sum
    const float* pp = g_partial + (size_t)img * NPIX + tid;
    float a[NCHUNK];
#pragma unroll
    for (int c = 0; c < NCHUNK; c++)
        a[c] = __ldg(pp + (size_t)c * NIMG * NPIX);
#pragma unroll
    for (int st = 1; st < NCHUNK; st <<= 1)
#pragma unroll
        for (int c = 0; c < NCHUNK; c += 2 * st)
            a[c] += a[c + st];
    float val = a[0];

    // orderable key: (monotone float bits : 1023 - pix) -> max == JAX order
    uint32_t fb = __float_as_uint(val);
    fb = (fb & 0x80000000u) ? ~fb : (fb | 0x80000000u);
    unsigned long long key =
        ((unsigned long long)fb << 32) | (uint32_t)(NPIX - 1 - tid);

    // per-warp bitonic sort, DESCENDING (lane 0 = max). Keys unique.
#pragma unroll
    for (int k = 2; k <= 32; k <<= 1) {
#pragma unroll
        for (int jj = k >> 1; jj > 0; jj >>= 1) {
            unsigned long long o = __shfl_xor_sync(0xffffffffu, key, jj);
            bool dirAsc  = ((lane & k) != 0);
            bool isLower = ((lane & jj) == 0);
            bool takeMin = (dirAsc == isLower);
            key = takeMin ? (key < o ? key : o) : (key > o ? key : o);
        }
    }
    // store sorted top-20 column-major; row 20 = sentinel zeros
    if (lane <= KTOP)
        s_lists[lane * 32 + warp] = (lane < KTOP) ? key : 0ull;
    __syncthreads();

    // exact 32-way tournament merge on warp 0, REDUX-based rounds
    if (warp == 0) {
        int h = 0;
        unsigned long long head = s_lists[lane];   // head of list `lane`
        for (int r = 0; r < KTOP; r++) {
            uint32_t hi = (uint32_t)(head >> 32);
            uint32_t lo = (uint32_t)head;
            uint32_t m1 = __reduce_max_sync(0xffffffffu, hi);
            uint32_t lo2 = (hi == m1) ? lo : 0u;
            uint32_t m2 = __reduce_max_sync(0xffffffffu, lo2);
            if (hi == m1 && lo == m2) {            // unique winner
                int pix = NPIX - 1 - (int)(lo & 1023u);
                int X = pix & 31, Y = pix >> 5;
                out[              img * PTOT + r] = (float)(X < 1 ? 1 : X);
                out[NIMG * PTOT + img * PTOT + r] = (float)(Y < 1 ? 1 : Y);
                s_flag[pix] = 1;
                h++;
                head = s_lists[h * 32 + lane];     // h <= 20 -> sentinel row
            }
        }
    }
    __syncthreads();

    // unselected positions via ballot + warp-0 scan of warp counts
    bool sel = (s_flag[tid] != 0);
    unsigned bal = __ballot_sync(0xffffffffu, sel);
    if (lane == 0) warpcnt[warp] = __popc(bal);
    __syncthreads();
    if (warp == 0) {
        int v = warpcnt[lane], sc = v;
#pragma unroll
        for (int off = 1; off < 32; off <<= 1) {
            int o = __shfl_up_sync(0xffffffffu, sc, off);
            if (lane >= off) sc += o;
        }
        warpcnt[lane] = sc - v;      // exclusive prefix
    }
    __syncthreads();
    int before = warpcnt[warp] + __popc(bal & ((1u << lane) - 1u));

    if (!sel) {
        int u = tid - before;           // position among unselected (0..1003)
        int jx = s_invp[u];
        if (jx >= 0) {
            int X = tid & 31, Y = tid >> 5;
            out[              img * PTOT + KTOP + jx] = (float)(X < 1 ? 1 : X);
            out[NIMG * PTOT + img * PTOT + KTOP + jx] = (float)(Y < 1 ? 1 : Y);
        }
    }
}

extern "C" void kernel_launch(void* const* d_in, const int* in_sizes, int n_in,
                              void* d_out, int out_size) {
    const float* feature = (const float*)d_in[0];
    const float* dww     = (const float*)d_in[1];
    const float* pww     = (const float*)d_in[3];
    float* out = (float*)d_out;

    patch_vote_kA<<<NPERMBLK + NCHUNK * NIMG, 256>>>(feature, dww, pww);
    patch_vote_kB<<<NIMG, 1024>>>(out);
}